// round 7
// baseline (speedup 1.0000x reference)
#include <cuda_runtime.h>
#include <cuda_bf16.h>
#include <math.h>

#define NB 4
#define NL 512
#define ND 256
#define NH 128
#define NEGV (-1e30f)

// ---------------- scratch (device globals) ----------------
__device__ float g_P[NB*NL*NH];        // exp(2*own)
__device__ float g_Q[NB*NL*NH];        // exp(2*comp)
__device__ float g_C[NB*NL*ND];        // attention context
__device__ float g_inp[NB*NL*2*ND];    // gated GRU input
__device__ float g_xp[2*NB*NL*384];    // GRU input projections [dir][b*L][3H]

__device__ __forceinline__ float frcp(float x) {
    float r; asm("rcp.approx.f32 %0, %1;" : "=f"(r) : "f"(x)); return r;
}
__device__ __forceinline__ float fsig(float x) {
    return frcp(1.0f + __expf(-x));
}
__device__ __forceinline__ float ftanh(float x) {
    return 1.0f - 2.0f * frcp(__expf(2.0f * x) + 1.0f);
}
__device__ __forceinline__ unsigned long long fma2(unsigned long long a,
                                                   unsigned long long b,
                                                   unsigned long long c) {
    unsigned long long d;
    asm("fma.rn.f32x2 %0, %1, %2, %3;" : "=l"(d) : "l"(a), "l"(b), "l"(c));
    return d;
}
__device__ __forceinline__ unsigned long long pkdup(float v) {
    unsigned long long d;
    asm("mov.b64 %0, {%1,%1};" : "=l"(d) : "f"(v));
    return d;
}
__device__ __forceinline__ float2 upk(unsigned long long v) {
    float2 r;
    asm("mov.b64 {%0,%1}, %2;" : "=f"(r.x), "=f"(r.y) : "l"(v));
    return r;
}

// ---------------- unified smem-tiled SGEMM (64x128x16 tiles, 4x8 microtile) -------
// Reads original row-major weights W[n][k]; transposes into smem per tile.
// EPI: 0 = proj (exp(2*(z+b)) -> g_P/g_Q), 1 = gate (inp*sig(z+b) -> g_inp),
//      2 = xp (z+b -> g_xp per-direction layout)
#define AST 68
#define BST 132
template<int KDIM, int NDIM, int NSPLIT, int EPI>
__global__ void __launch_bounds__(256) k_gemm(const float* __restrict__ A,
                                              const float* __restrict__ Aalt,
                                              const float* __restrict__ W1,
                                              const float* __restrict__ W2,
                                              const float* __restrict__ b1,
                                              const float* __restrict__ b2) {
    __shared__ float As[16*AST];   // [k][m]
    __shared__ float Bs[16*BST];   // [k][n]
    const int NT = NDIM / 128;
    const int KT = KDIM / 16;
    int tid = threadIdx.x;
    int ntI = blockIdx.x % NT, mtI = blockIdx.x / NT;
    int m0 = mtI * 64, n0 = ntI * 128;

    int arow = tid & 63,  akc = (tid >> 6) * 4;  // A: 64 rows x 4 k-slots of 4
    int bnr  = tid & 127, bkc = (tid >> 7) * 8;  // B: 128 n-rows x 2 k-slots of 8
    int nr = n0 + bnr;
    const float* wrow = (NSPLIT < NDIM && nr >= NSPLIT) ? (W2 + (nr - NSPLIT)*KDIM)
                                                        : (W1 + nr*KDIM);

    // first prefetch (kt = 0)
    float4 pa, pb0, pb1;
    {
        int kg = akc;
        const float* src;
        if (EPI == 1) src = (kg < 256) ? (A + (m0+arow)*256 + kg)
                                       : (Aalt + (m0+arow)*256 + kg - 256);
        else          src = A + (m0+arow)*KDIM + kg;
        pa  = *(const float4*)src;
        pb0 = *(const float4*)(wrow + bkc);
        pb1 = *(const float4*)(wrow + bkc + 4);
    }

    int tx = tid & 15, ty = tid >> 4;
    unsigned long long acc[4][4];
    #pragma unroll
    for (int r = 0; r < 4; ++r)
        #pragma unroll
        for (int c = 0; c < 4; ++c) acc[r][c] = 0ull;

    for (int kt = 0; kt < KT; ++kt) {
        As[(akc+0)*AST + arow] = pa.x;
        As[(akc+1)*AST + arow] = pa.y;
        As[(akc+2)*AST + arow] = pa.z;
        As[(akc+3)*AST + arow] = pa.w;
        Bs[(bkc+0)*BST + bnr] = pb0.x;
        Bs[(bkc+1)*BST + bnr] = pb0.y;
        Bs[(bkc+2)*BST + bnr] = pb0.z;
        Bs[(bkc+3)*BST + bnr] = pb0.w;
        Bs[(bkc+4)*BST + bnr] = pb1.x;
        Bs[(bkc+5)*BST + bnr] = pb1.y;
        Bs[(bkc+6)*BST + bnr] = pb1.z;
        Bs[(bkc+7)*BST + bnr] = pb1.w;
        __syncthreads();
        if (kt + 1 < KT) {
            int kg = (kt+1)*16 + akc;
            const float* src;
            if (EPI == 1) src = (kg < 256) ? (A + (m0+arow)*256 + kg)
                                           : (Aalt + (m0+arow)*256 + kg - 256);
            else          src = A + (m0+arow)*KDIM + kg;
            pa  = *(const float4*)src;
            pb0 = *(const float4*)(wrow + (kt+1)*16 + bkc);
            pb1 = *(const float4*)(wrow + (kt+1)*16 + bkc + 4);
        }
        #pragma unroll
        for (int k = 0; k < 16; ++k) {
            float4 av = *(const float4*)(As + k*AST + ty*4);
            ulonglong2 bpA = *(const ulonglong2*)(Bs + k*BST + tx*8);
            ulonglong2 bpB = *(const ulonglong2*)(Bs + k*BST + tx*8 + 4);
            unsigned long long a0 = pkdup(av.x);
            unsigned long long a1 = pkdup(av.y);
            unsigned long long a2 = pkdup(av.z);
            unsigned long long a3 = pkdup(av.w);
            acc[0][0] = fma2(a0, bpA.x, acc[0][0]); acc[0][1] = fma2(a0, bpA.y, acc[0][1]);
            acc[0][2] = fma2(a0, bpB.x, acc[0][2]); acc[0][3] = fma2(a0, bpB.y, acc[0][3]);
            acc[1][0] = fma2(a1, bpA.x, acc[1][0]); acc[1][1] = fma2(a1, bpA.y, acc[1][1]);
            acc[1][2] = fma2(a1, bpB.x, acc[1][2]); acc[1][3] = fma2(a1, bpB.y, acc[1][3]);
            acc[2][0] = fma2(a2, bpA.x, acc[2][0]); acc[2][1] = fma2(a2, bpA.y, acc[2][1]);
            acc[2][2] = fma2(a2, bpB.x, acc[2][2]); acc[2][3] = fma2(a2, bpB.y, acc[2][3]);
            acc[3][0] = fma2(a3, bpA.x, acc[3][0]); acc[3][1] = fma2(a3, bpA.y, acc[3][1]);
            acc[3][2] = fma2(a3, bpB.x, acc[3][2]); acc[3][3] = fma2(a3, bpB.y, acc[3][3]);
        }
        __syncthreads();
    }

    // epilogue: two float4 column groups per row: cols cg0 and cg0+4
    int cg0 = n0 + tx*8;
    #pragma unroll
    for (int g = 0; g < 2; ++g) {
        int cg = cg0 + g*4;
        const float* bsrc = (NSPLIT < NDIM && cg >= NSPLIT) ? (b2 + cg - NSPLIT) : (b1 + cg);
        float4 bb = *(const float4*)bsrc;
        #pragma unroll
        for (int r = 0; r < 4; ++r) {
            int row = m0 + ty*4 + r;
            float2 zlo = upk(acc[r][g*2 + 0]);
            float2 zhi = upk(acc[r][g*2 + 1]);
            float4 z = make_float4(zlo.x + bb.x, zlo.y + bb.y, zhi.x + bb.z, zhi.y + bb.w);
            if (EPI == 0) {
                float4 y;
                y.x = __expf(2.f*z.x); y.y = __expf(2.f*z.y);
                y.z = __expf(2.f*z.z); y.w = __expf(2.f*z.w);
                float* outp = (cg < 128) ? (g_P + row*128 + cg) : (g_Q + row*128 + cg - 128);
                *(float4*)outp = y;
            } else if (EPI == 1) {
                const float* isrc = (cg < 256) ? (A + row*256 + cg) : (Aalt + row*256 + cg - 256);
                float4 inp = *(const float4*)isrc;
                float4 y;
                y.x = inp.x * fsig(z.x); y.y = inp.y * fsig(z.y);
                y.z = inp.z * fsig(z.z); y.w = inp.w * fsig(z.w);
                *(float4*)(g_inp + row*512 + cg) = y;
            } else {
                int dir = (cg >= 384) ? 1 : 0;
                int cL = cg - dir*384;
                *(float4*)(g_xp + dir*(NB*NL*384) + row*384 + cL) = z;
            }
        }
    }
}

// ---------------- K2: fused scores + softmax + context ----------------
// tanh(a+b) = 1 - 2/(P*Q+1), P = e^{2a}, Q = e^{2b}
#define PST 130
#define SST 513
__global__ void __launch_bounds__(256) k_attn(const float* __restrict__ v,
                                              const float* __restrict__ v_attn,
                                              const int* __restrict__ lengths) {
    __shared__ float Psh[8*PST];
    __shared__ float QV[4160];       // Q tile 32x130 / v tile 16x256
    __shared__ float ssh[8*SST];
    __shared__ float vash[128];
    __shared__ float s_sv;

    int tid = threadIdx.x;
    int b  = blockIdx.x >> 6;
    int qt = blockIdx.x & 63;
    int qrow0 = b*NL + qt*8;
    int len = lengths[b];

    for (int i = tid; i < 8*128; i += 256) {
        int q = i >> 7, h = i & 127;
        Psh[q*PST + h] = g_P[(qrow0 + q)*128 + h];
    }
    if (tid < 128) vash[tid] = -2.0f * v_attn[tid];
    if (tid == 0) {
        float s = 0.f;
        for (int h = 0; h < 128; ++h) s += v_attn[h];
        s_sv = s;
    }

    int q = tid & 7, kslot = tid >> 3;   // 32 k slots
    // ---- phase A: scores ----
    for (int kt = 0; kt < 16; ++kt) {
        int kb = kt * 32;
        if (kb < len) {                   // uniform branch per block
            __syncthreads();
            for (int i = tid; i < 32*128; i += 256) {
                int k = i >> 7, h = i & 127;
                QV[k*PST + h] = g_Q[(b*NL + kb + k)*128 + h];
            }
            __syncthreads();
            float sv = s_sv;
            const float2* Pp = (const float2*)(Psh + q*PST);
            const float2* vp = (const float2*)vash;
            const float2* Qp = (const float2*)(QV + kslot*PST);
            float acc = 0.f;
            #pragma unroll
            for (int hh = 0; hh < 64; ++hh) {
                float2 p  = Pp[hh];
                float2 qq = Qp[hh];
                float2 va = vp[hh];
                acc = fmaf(va.x, frcp(fmaf(p.x, qq.x, 1.0f)), acc);
                acc = fmaf(va.y, frcp(fmaf(p.y, qq.y, 1.0f)), acc);
            }
            int kg = kb + kslot;
            ssh[q*SST + kg] = (kg < len) ? (sv + acc) : NEGV;
        } else {
            ssh[q*SST + kb + kslot] = NEGV;
        }
    }
    __syncthreads();

    // ---- phase B: softmax over k (8 warps, 1 q each) ----
    int wid = tid >> 5, lane = tid & 31;
    {
        float* srow = ssh + wid*SST;
        float m = -3.4e38f;
        for (int k = lane; k < 512; k += 32) m = fmaxf(m, srow[k]);
        #pragma unroll
        for (int o = 16; o; o >>= 1) m = fmaxf(m, __shfl_xor_sync(0xffffffffu, m, o));
        float s = 0.f;
        for (int k = lane; k < 512; k += 32) { float e = __expf(srow[k] - m); srow[k] = e; s += e; }
        #pragma unroll
        for (int o = 16; o; o >>= 1) s += __shfl_xor_sync(0xffffffffu, s, o);
        float inv = frcp(s);
        for (int k = lane; k < 512; k += 32) srow[k] *= inv;
    }

    // ---- phase C: context C = attn @ v ----
    int dl = tid & 63, qg = tid >> 6;  // qg 0..3, rows qg and qg+4
    float4 acc0 = make_float4(0.f,0.f,0.f,0.f);
    float4 acc1 = make_float4(0.f,0.f,0.f,0.f);
    for (int kt = 0; kt < 32; ++kt) {
        int kb = kt * 16;
        if (kb >= len) break;            // uniform: attn is 0 there
        __syncthreads();
        {
            const float4* src = (const float4*)(v + (b*NL + kb)*256);
            float4* dst = (float4*)QV;
            #pragma unroll
            for (int i = 0; i < 4; ++i) dst[tid + i*256] = src[tid + i*256];
        }
        __syncthreads();
        #pragma unroll 4
        for (int kk = 0; kk < 16; ++kk) {
            float4 vv = ((const float4*)QV)[kk*64 + dl];
            float a0 = ssh[qg*SST + kb + kk];
            float a1 = ssh[(qg+4)*SST + kb + kk];
            acc0.x = fmaf(a0, vv.x, acc0.x); acc0.y = fmaf(a0, vv.y, acc0.y);
            acc0.z = fmaf(a0, vv.z, acc0.z); acc0.w = fmaf(a0, vv.w, acc0.w);
            acc1.x = fmaf(a1, vv.x, acc1.x); acc1.y = fmaf(a1, vv.y, acc1.y);
            acc1.z = fmaf(a1, vv.z, acc1.z); acc1.w = fmaf(a1, vv.w, acc1.w);
        }
    }
    ((float4*)(g_C + (qrow0 + qg)*256))[dl] = acc0;
    ((float4*)(g_C + (qrow0 + qg + 4)*256))[dl] = acc1;
}

// ---------------- K5: bidirectional GRU scan (f32x2 + early exit) ----------------
__global__ void __launch_bounds__(384, 1) k_gru(const int* __restrict__ lengths,
                                                const float* __restrict__ w_hh_f,
                                                const float* __restrict__ w_hh_b,
                                                const float* __restrict__ b_hh_f,
                                                const float* __restrict__ b_hh_b,
                                                float* __restrict__ out) {
    __shared__ ulonglong2 h2v[32];   // h[128] as f32x2 pairs
    __shared__ float hp[384];

    int dir = blockIdx.x & 1;
    int b   = blockIdx.x >> 1;
    int j   = threadIdx.x;   // 0..383: owns hp row j
    int len = lengths[b];
    const float* whh = (dir ? w_hh_b : w_hh_f) + j*128;
    float bhh = (dir ? b_hh_b : b_hh_f)[j];
    float* hf = (float*)h2v;

    unsigned long long w2[64];
    {
        const ulonglong2* wpk = (const ulonglong2*)whh;
        #pragma unroll
        for (int k = 0; k < 32; ++k) {
            ulonglong2 t = wpk[k];
            w2[2*k] = t.x; w2[2*k+1] = t.y;
        }
    }

    // zero-fill out rows l in [len, NL)
    {
        int n = (NL - len) * 128;
        for (int i = j; i < n; i += 384) {
            int l = len + (i >> 7);
            out[(b*NL + l)*256 + dir*128 + (i & 127)] = 0.0f;
        }
    }

    if (j < 32) h2v[j] = make_ulonglong2(0ull, 0ull);
    __syncthreads();

    const float* xpbase = g_xp + dir*(NB*NL*384) + b*NL*384;

    float xr_c = 0.f, xz_c = 0.f, xn_c = 0.f;
    if (j < 128) {
        int l0 = dir ? (len-1) : 0;
        const float* p = xpbase + l0*384 + j;
        xr_c = p[0]; xz_c = p[128]; xn_c = p[256];
    }

    for (int t = 0; t < len; ++t) {
        int l = dir ? (len-1-t) : t;
        // matvec: hp[j] = bhh + w_hh[j,:] . h
        unsigned long long a0 = 0ull, a1 = 0ull, a2 = 0ull, a3 = 0ull;
        #pragma unroll
        for (int k = 0; k < 32; k += 2) {
            ulonglong2 hA = h2v[k];
            ulonglong2 hB = h2v[k+1];
            a0 = fma2(w2[2*k],   hA.x, a0);
            a1 = fma2(w2[2*k+1], hA.y, a1);
            a2 = fma2(w2[2*k+2], hB.x, a2);
            a3 = fma2(w2[2*k+3], hB.y, a3);
        }
        float s = bhh;
        s += __uint_as_float((unsigned)(a0 & 0xffffffffull)) + __uint_as_float((unsigned)(a0 >> 32));
        s += __uint_as_float((unsigned)(a1 & 0xffffffffull)) + __uint_as_float((unsigned)(a1 >> 32));
        s += __uint_as_float((unsigned)(a2 & 0xffffffffull)) + __uint_as_float((unsigned)(a2 >> 32));
        s += __uint_as_float((unsigned)(a3 & 0xffffffffull)) + __uint_as_float((unsigned)(a3 >> 32));
        hp[j] = s;
        __syncthreads();
        if (j < 128) {
            float r = fsig(xr_c + hp[j]);
            float z = fsig(xz_c + hp[j + 128]);
            float n = ftanh(xn_c + r * hp[j + 256]);
            float hold = hf[j];
            float hnew = (1.0f - z) * n + z * hold;
            hf[j] = hnew;
            out[(b*NL + l)*256 + dir*128 + j] = hnew;
            if (t + 1 < len) {
                int ln = dir ? (len-2-t) : (t+1);
                const float* p = xpbase + ln*384 + j;
                xr_c = p[0]; xz_c = p[128]; xn_c = p[256];
            }
        }
        __syncthreads();
    }
}

extern "C" void kernel_launch(void* const* d_in, const int* in_sizes, int n_in,
                              void* d_out, int out_size) {
    const float* v      = (const float*)d_in[0];
    const int*   lens   = (const int*)d_in[1];
    // d_in[2] = p_mask (unused; derived from lengths)
    const float* own_W  = (const float*)d_in[3];
    const float* own_b  = (const float*)d_in[4];
    const float* comp_W = (const float*)d_in[5];
    const float* comp_b = (const float*)d_in[6];
    const float* v_attn = (const float*)d_in[7];
    const float* gate_W = (const float*)d_in[8];
    const float* gate_b = (const float*)d_in[9];
    const float* w_ih_f = (const float*)d_in[10];
    const float* w_hh_f = (const float*)d_in[11];
    const float* b_ih_f = (const float*)d_in[12];
    const float* b_hh_f = (const float*)d_in[13];
    const float* w_ih_b = (const float*)d_in[14];
    const float* w_hh_b = (const float*)d_in[15];
    const float* b_ih_b = (const float*)d_in[16];
    const float* b_hh_b = (const float*)d_in[17];
    float* out = (float*)d_out;

    float* d_C;   cudaGetSymbolAddress((void**)&d_C,   g_C);
    float* d_inp; cudaGetSymbolAddress((void**)&d_inp, g_inp);

    k_gemm<256, 256, 128, 0><<<32*2, 256>>>(v, nullptr, own_W, comp_W, own_b, comp_b);
    k_attn<<<NB*(NL/8), 256>>>(v, v_attn, lens);
    k_gemm<512, 512, 512, 1><<<32*4, 256>>>(v, d_C, gate_W, gate_W, gate_b, gate_b);
    k_gemm<512, 768, 384, 2><<<32*6, 256>>>(d_inp, nullptr, w_ih_f, w_ih_b, b_ih_f, b_ih_b);
    k_gru<<<2*NB, 384>>>(lens, w_hh_f, w_hh_b, b_hh_f, b_hh_b, out);
}

// round 8
// speedup vs baseline: 1.2360x; 1.2360x over previous
#include <cuda_runtime.h>
#include <cuda_bf16.h>
#include <math.h>

#define NB 4
#define NL 512
#define ND 256
#define NH 128
#define NEGV (-1e30f)

// ---------------- scratch (device globals) ----------------
__device__ float g_P[NB*NL*NH];        // exp(2*own)
__device__ float g_Q[NB*NL*NH];        // exp(2*comp)
__device__ float g_C[NB*NL*ND];        // attention context
__device__ float g_inp[NB*NL*2*ND];    // gated GRU input
__device__ float g_xp[2*NB*NL*384];    // GRU input projections [dir][b*L][3H]

__device__ __forceinline__ float frcp(float x) {
    float r; asm("rcp.approx.f32 %0, %1;" : "=f"(r) : "f"(x)); return r;
}
__device__ __forceinline__ float fsig(float x) {
    return frcp(1.0f + __expf(-x));
}
__device__ __forceinline__ float ftanh(float x) {
    return 1.0f - 2.0f * frcp(__expf(2.0f * x) + 1.0f);
}
__device__ __forceinline__ unsigned long long fma2(unsigned long long a,
                                                   unsigned long long b,
                                                   unsigned long long c) {
    unsigned long long d;
    asm("fma.rn.f32x2 %0, %1, %2, %3;" : "=l"(d) : "l"(a), "l"(b), "l"(c));
    return d;
}
__device__ __forceinline__ unsigned long long add2(unsigned long long a,
                                                   unsigned long long b) {
    unsigned long long d;
    asm("add.rn.f32x2 %0, %1, %2;" : "=l"(d) : "l"(a), "l"(b));
    return d;
}
__device__ __forceinline__ unsigned long long pkdup(float v) {
    unsigned long long d;
    asm("mov.b64 %0, {%1,%1};" : "=l"(d) : "f"(v));
    return d;
}
__device__ __forceinline__ float2 upk(unsigned long long v) {
    float2 r;
    asm("mov.b64 {%0,%1}, %2;" : "=f"(r.x), "=f"(r.y) : "l"(v));
    return r;
}

// ---------------- unified smem-tiled SGEMM (64x64x16 tiles, double-buffered) ------
// Reads original row-major weights W[n][k]; transposes into smem per tile.
// EPI: 0 = proj (exp(2*(z+b)) -> g_P/g_Q), 1 = gate (inp*sig(z+b) -> g_inp),
//      2 = xp (z+b -> g_xp per-direction layout)
template<int KDIM, int NDIM, int NSPLIT, int EPI>
__global__ void __launch_bounds__(256) k_gemm(const float* __restrict__ A,
                                              const float* __restrict__ Aalt,
                                              const float* __restrict__ W1,
                                              const float* __restrict__ W2,
                                              const float* __restrict__ b1,
                                              const float* __restrict__ b2) {
    __shared__ float As[2][16*68];   // [buf][k][m], stride 68
    __shared__ float Bs[2][16*68];   // [buf][k][n], stride 68
    const int NT = NDIM / 64;
    const int KT = KDIM / 16;
    int tid = threadIdx.x;
    int ntI = blockIdx.x % NT, mtI = blockIdx.x / NT;
    int m0 = mtI * 64, n0 = ntI * 64;

    int arow = tid >> 2, akc = (tid & 3) * 4;   // A: 64 rows x 4 k-slots
    int bnr  = tid >> 2, bkc = (tid & 3) * 4;   // B: 64 n-rows x 4 k-slots
    int nr = n0 + bnr;
    const float* wrow = (NSPLIT < NDIM && nr >= NSPLIT) ? (W2 + (nr - NSPLIT)*KDIM)
                                                        : (W1 + nr*KDIM);

    // load kt = 0 into buffer 0
    float4 pa, pb;
    {
        const float* src;
        if (EPI == 1) src = (akc < 256) ? (A + (m0+arow)*256 + akc)
                                        : (Aalt + (m0+arow)*256 + akc - 256);
        else          src = A + (m0+arow)*KDIM + akc;
        pa = *(const float4*)src;
        pb = *(const float4*)(wrow + bkc);
    }
    As[0][(akc+0)*68 + arow] = pa.x;
    As[0][(akc+1)*68 + arow] = pa.y;
    As[0][(akc+2)*68 + arow] = pa.z;
    As[0][(akc+3)*68 + arow] = pa.w;
    Bs[0][(bkc+0)*68 + bnr] = pb.x;
    Bs[0][(bkc+1)*68 + bnr] = pb.y;
    Bs[0][(bkc+2)*68 + bnr] = pb.z;
    Bs[0][(bkc+3)*68 + bnr] = pb.w;
    __syncthreads();

    int tx = tid & 15, ty = tid >> 4;
    unsigned long long acc[4][2];
    #pragma unroll
    for (int r = 0; r < 4; ++r) { acc[r][0] = 0ull; acc[r][1] = 0ull; }

    for (int kt = 0; kt < KT; ++kt) {
        int cur = kt & 1, nxt = cur ^ 1;
        bool more = (kt + 1 < KT);
        if (more) {
            int kg = (kt+1)*16 + akc;
            const float* src;
            if (EPI == 1) src = (kg < 256) ? (A + (m0+arow)*256 + kg)
                                           : (Aalt + (m0+arow)*256 + kg - 256);
            else          src = A + (m0+arow)*KDIM + kg;
            pa = *(const float4*)src;
            pb = *(const float4*)(wrow + (kt+1)*16 + bkc);
        }
        const float* Asc = As[cur];
        const float* Bsc = Bs[cur];
        #pragma unroll
        for (int k = 0; k < 16; ++k) {
            ulonglong2 bp = *(const ulonglong2*)(Bsc + k*68 + tx*4);
            float4 av = *(const float4*)(Asc + k*68 + ty*4);
            unsigned long long a0 = pkdup(av.x);
            unsigned long long a1 = pkdup(av.y);
            unsigned long long a2 = pkdup(av.z);
            unsigned long long a3 = pkdup(av.w);
            acc[0][0] = fma2(a0, bp.x, acc[0][0]); acc[0][1] = fma2(a0, bp.y, acc[0][1]);
            acc[1][0] = fma2(a1, bp.x, acc[1][0]); acc[1][1] = fma2(a1, bp.y, acc[1][1]);
            acc[2][0] = fma2(a2, bp.x, acc[2][0]); acc[2][1] = fma2(a2, bp.y, acc[2][1]);
            acc[3][0] = fma2(a3, bp.x, acc[3][0]); acc[3][1] = fma2(a3, bp.y, acc[3][1]);
        }
        if (more) {
            As[nxt][(akc+0)*68 + arow] = pa.x;
            As[nxt][(akc+1)*68 + arow] = pa.y;
            As[nxt][(akc+2)*68 + arow] = pa.z;
            As[nxt][(akc+3)*68 + arow] = pa.w;
            Bs[nxt][(bkc+0)*68 + bnr] = pb.x;
            Bs[nxt][(bkc+1)*68 + bnr] = pb.y;
            Bs[nxt][(bkc+2)*68 + bnr] = pb.z;
            Bs[nxt][(bkc+3)*68 + bnr] = pb.w;
            __syncthreads();
        }
    }

    int cg = n0 + tx*4;
    const float* bsrc = (NSPLIT < NDIM && cg >= NSPLIT) ? (b2 + cg - NSPLIT) : (b1 + cg);
    float4 bb = *(const float4*)bsrc;
    #pragma unroll
    for (int r = 0; r < 4; ++r) {
        int row = m0 + ty*4 + r;
        float2 z01 = upk(acc[r][0]);
        float2 z23 = upk(acc[r][1]);
        float4 z = make_float4(z01.x + bb.x, z01.y + bb.y, z23.x + bb.z, z23.y + bb.w);
        if (EPI == 0) {
            float4 y;
            y.x = __expf(2.f*z.x); y.y = __expf(2.f*z.y);
            y.z = __expf(2.f*z.z); y.w = __expf(2.f*z.w);
            float* outp = (cg < 128) ? (g_P + row*128 + cg) : (g_Q + row*128 + cg - 128);
            *(float4*)outp = y;
        } else if (EPI == 1) {
            const float* isrc = (cg < 256) ? (A + row*256 + cg) : (Aalt + row*256 + cg - 256);
            float4 inp = *(const float4*)isrc;
            float4 y;
            y.x = inp.x * fsig(z.x); y.y = inp.y * fsig(z.y);
            y.z = inp.z * fsig(z.z); y.w = inp.w * fsig(z.w);
            *(float4*)(g_inp + row*512 + cg) = y;
        } else {
            int dir = (cg >= 384) ? 1 : 0;
            int cL = cg - dir*384;
            *(float4*)(g_xp + dir*(NB*NL*384) + row*384 + cL) = z;
        }
    }
}

// ---------------- K2: fused scores + softmax + context ----------------
// tanh(a+b) = 1 - 2/(P*Q+1), P = e^{2a}, Q = e^{2b}
#define PST 130
#define SST 513
__global__ void __launch_bounds__(256) k_attn(const float* __restrict__ v,
                                              const float* __restrict__ v_attn,
                                              const int* __restrict__ lengths) {
    __shared__ float Psh[8*PST];
    __shared__ float QV[4160];       // Q tile 32x130 / v tile 16x256
    __shared__ float ssh[8*SST];
    __shared__ float vash[128];
    __shared__ float s_sv;

    int tid = threadIdx.x;
    int b  = blockIdx.x >> 6;
    int qt = blockIdx.x & 63;
    int qrow0 = b*NL + qt*8;
    int len = lengths[b];

    for (int i = tid; i < 8*128; i += 256) {
        int q = i >> 7, h = i & 127;
        Psh[q*PST + h] = g_P[(qrow0 + q)*128 + h];
    }
    if (tid < 128) vash[tid] = -2.0f * v_attn[tid];
    if (tid == 0) {
        float s = 0.f;
        for (int h = 0; h < 128; ++h) s += v_attn[h];
        s_sv = s;
    }

    int q = tid & 7, kslot = tid >> 3;   // 32 k slots
    // ---- phase A: scores ----
    for (int kt = 0; kt < 16; ++kt) {
        int kb = kt * 32;
        if (kb < len) {                   // uniform branch per block
            __syncthreads();
            for (int i = tid; i < 32*128; i += 256) {
                int k = i >> 7, h = i & 127;
                QV[k*PST + h] = g_Q[(b*NL + kb + k)*128 + h];
            }
            __syncthreads();
            float sv = s_sv;
            const float2* Pp = (const float2*)(Psh + q*PST);
            const float2* vp = (const float2*)vash;
            const float2* Qp = (const float2*)(QV + kslot*PST);
            float acc = 0.f;
            #pragma unroll
            for (int hh = 0; hh < 64; ++hh) {
                float2 p  = Pp[hh];
                float2 qq = Qp[hh];
                float2 va = vp[hh];
                acc = fmaf(va.x, frcp(fmaf(p.x, qq.x, 1.0f)), acc);
                acc = fmaf(va.y, frcp(fmaf(p.y, qq.y, 1.0f)), acc);
            }
            int kg = kb + kslot;
            ssh[q*SST + kg] = (kg < len) ? (sv + acc) : NEGV;
        } else {
            ssh[q*SST + kb + kslot] = NEGV;
        }
    }
    __syncthreads();

    // ---- phase B: softmax over k (8 warps, 1 q each) ----
    int wid = tid >> 5, lane = tid & 31;
    {
        float* srow = ssh + wid*SST;
        float m = -3.4e38f;
        for (int k = lane; k < 512; k += 32) m = fmaxf(m, srow[k]);
        #pragma unroll
        for (int o = 16; o; o >>= 1) m = fmaxf(m, __shfl_xor_sync(0xffffffffu, m, o));
        float s = 0.f;
        for (int k = lane; k < 512; k += 32) { float e = __expf(srow[k] - m); srow[k] = e; s += e; }
        #pragma unroll
        for (int o = 16; o; o >>= 1) s += __shfl_xor_sync(0xffffffffu, s, o);
        float inv = frcp(s);
        for (int k = lane; k < 512; k += 32) srow[k] *= inv;
    }

    // ---- phase C: context C = attn @ v (packed f32x2) ----
    int dl = tid & 63, qg = tid >> 6;  // qg 0..3, rows qg and qg+4
    unsigned long long acc0lo = 0ull, acc0hi = 0ull;
    unsigned long long acc1lo = 0ull, acc1hi = 0ull;
    for (int kt = 0; kt < 32; ++kt) {
        int kb = kt * 16;
        if (kb >= len) break;            // uniform: attn is 0 there
        __syncthreads();
        {
            const float4* src = (const float4*)(v + (b*NL + kb)*256);
            float4* dst = (float4*)QV;
            #pragma unroll
            for (int i = 0; i < 4; ++i) dst[tid + i*256] = src[tid + i*256];
        }
        __syncthreads();
        #pragma unroll 4
        for (int kk = 0; kk < 16; ++kk) {
            ulonglong2 vv = ((const ulonglong2*)QV)[kk*64 + dl];
            unsigned long long a0 = pkdup(ssh[qg*SST + kb + kk]);
            unsigned long long a1 = pkdup(ssh[(qg+4)*SST + kb + kk]);
            acc0lo = fma2(a0, vv.x, acc0lo); acc0hi = fma2(a0, vv.y, acc0hi);
            acc1lo = fma2(a1, vv.x, acc1lo); acc1hi = fma2(a1, vv.y, acc1hi);
        }
    }
    {
        float2 lo = upk(acc0lo), hi = upk(acc0hi);
        ((float4*)(g_C + (qrow0 + qg)*256))[dl] = make_float4(lo.x, lo.y, hi.x, hi.y);
        lo = upk(acc1lo); hi = upk(acc1hi);
        ((float4*)(g_C + (qrow0 + qg + 4)*256))[dl] = make_float4(lo.x, lo.y, hi.x, hi.y);
    }
}

// ---------------- K5: bidirectional GRU scan (f32x2 + early exit) ----------------
__global__ void __launch_bounds__(384, 1) k_gru(const int* __restrict__ lengths,
                                                const float* __restrict__ w_hh_f,
                                                const float* __restrict__ w_hh_b,
                                                const float* __restrict__ b_hh_f,
                                                const float* __restrict__ b_hh_b,
                                                float* __restrict__ out) {
    __shared__ ulonglong2 h2v[32];   // h[128] as f32x2 pairs
    __shared__ float hp[384];

    int dir = blockIdx.x & 1;
    int b   = blockIdx.x >> 1;
    int j   = threadIdx.x;   // 0..383: owns hp row j
    int len = lengths[b];
    const float* whh = (dir ? w_hh_b : w_hh_f) + j*128;
    float bhh = (dir ? b_hh_b : b_hh_f)[j];
    float* hf = (float*)h2v;

    unsigned long long w2[64];
    {
        const ulonglong2* wpk = (const ulonglong2*)whh;
        #pragma unroll
        for (int k = 0; k < 32; ++k) {
            ulonglong2 t = wpk[k];
            w2[2*k] = t.x; w2[2*k+1] = t.y;
        }
    }

    // zero-fill out rows l in [len, NL)
    {
        int n = (NL - len) * 128;
        for (int i = j; i < n; i += 384) {
            int l = len + (i >> 7);
            out[(b*NL + l)*256 + dir*128 + (i & 127)] = 0.0f;
        }
    }

    if (j < 32) h2v[j] = make_ulonglong2(0ull, 0ull);
    __syncthreads();

    const float* xpbase = g_xp + dir*(NB*NL*384) + b*NL*384;

    float xr_c = 0.f, xz_c = 0.f, xn_c = 0.f;
    if (j < 128) {
        int l0 = dir ? (len-1) : 0;
        const float* p = xpbase + l0*384 + j;
        xr_c = p[0]; xz_c = p[128]; xn_c = p[256];
    }

    for (int t = 0; t < len; ++t) {
        int l = dir ? (len-1-t) : t;
        // matvec: hp[j] = bhh + w_hh[j,:] . h
        unsigned long long a0 = 0ull, a1 = 0ull, a2 = 0ull, a3 = 0ull;
        #pragma unroll
        for (int k = 0; k < 32; k += 2) {
            ulonglong2 hA = h2v[k];
            ulonglong2 hB = h2v[k+1];
            a0 = fma2(w2[2*k],   hA.x, a0);
            a1 = fma2(w2[2*k+1], hA.y, a1);
            a2 = fma2(w2[2*k+2], hB.x, a2);
            a3 = fma2(w2[2*k+3], hB.y, a3);
        }
        unsigned long long sAB = add2(add2(a0, a1), add2(a2, a3));
        float2 sp = upk(sAB);
        hp[j] = bhh + sp.x + sp.y;
        __syncthreads();
        if (j < 128) {
            float r = fsig(xr_c + hp[j]);
            float z = fsig(xz_c + hp[j + 128]);
            float n = ftanh(xn_c + r * hp[j + 256]);
            float hold = hf[j];
            float hnew = (1.0f - z) * n + z * hold;
            hf[j] = hnew;
            out[(b*NL + l)*256 + dir*128 + j] = hnew;
            if (t + 1 < len) {
                int ln = dir ? (len-2-t) : (t+1);
                const float* p = xpbase + ln*384 + j;
                xr_c = p[0]; xz_c = p[128]; xn_c = p[256];
            }
        }
        __syncthreads();
    }
}

extern "C" void kernel_launch(void* const* d_in, const int* in_sizes, int n_in,
                              void* d_out, int out_size) {
    const float* v      = (const float*)d_in[0];
    const int*   lens   = (const int*)d_in[1];
    // d_in[2] = p_mask (unused; derived from lengths)
    const float* own_W  = (const float*)d_in[3];
    const float* own_b  = (const float*)d_in[4];
    const float* comp_W = (const float*)d_in[5];
    const float* comp_b = (const float*)d_in[6];
    const float* v_attn = (const float*)d_in[7];
    const float* gate_W = (const float*)d_in[8];
    const float* gate_b = (const float*)d_in[9];
    const float* w_ih_f = (const float*)d_in[10];
    const float* w_hh_f = (const float*)d_in[11];
    const float* b_ih_f = (const float*)d_in[12];
    const float* b_hh_f = (const float*)d_in[13];
    const float* w_ih_b = (const float*)d_in[14];
    const float* w_hh_b = (const float*)d_in[15];
    const float* b_ih_b = (const float*)d_in[16];
    const float* b_hh_b = (const float*)d_in[17];
    float* out = (float*)d_out;

    float* d_C;   cudaGetSymbolAddress((void**)&d_C,   g_C);
    float* d_inp; cudaGetSymbolAddress((void**)&d_inp, g_inp);

    k_gemm<256, 256, 128, 0><<<32*4, 256>>>(v, nullptr, own_W, comp_W, own_b, comp_b);
    k_attn<<<NB*(NL/8), 256>>>(v, v_attn, lens);
    k_gemm<512, 512, 512, 1><<<32*8, 256>>>(v, d_C, gate_W, gate_W, gate_b, gate_b);
    k_gemm<512, 768, 384, 2><<<32*12, 256>>>(d_inp, nullptr, w_ih_f, w_ih_b, b_ih_f, b_ih_b);
    k_gru<<<2*NB, 384>>>(lens, w_hh_f, w_hh_b, b_hh_f, b_hh_b, out);
}